// round 16
// baseline (speedup 1.0000x reference)
#include <cuda_runtime.h>
#include <cooperative_groups.h>
#include <math.h>

namespace cg = cooperative_groups;

#define B_ 32
#define T_ 32
#define F_ 64
#define H_ 256
#define N_ 1024
#define A_ 64
#define C_ 192
#define M_ 256
#define HSOFF (T_*H_*B_)

// ---------------- precomputed globals ----------------
__device__ __align__(16) float g_addrT[A_*N_];     // addrT[a*1024+n]
__device__ __align__(16) float g_giA[T_*B_*768];   // gi: [(t*32+b)*768+row]
__device__ __align__(16) float g_cxA[T_*B_*C_];    // Wci@x: [(t*32+b)*192+c]
__device__ __align__(16) float g_WhT[H_*768];      // [k*768+row]
__device__ __align__(16) float g_WqT[H_*M_];       // [k*256+m]
__device__ __align__(16) float g_WchT[H_*C_];      // [k*192+c]
__device__ __align__(16) float g_WmT[M_*768];      // [m*768+row]

__device__ __forceinline__ float warp_sum(float v) {
    #pragma unroll
    for (int o = 16; o; o >>= 1) v += __shfl_xor_sync(0xffffffffu, v, o);
    return v;
}
__device__ __forceinline__ float warp_max(float v) {
    #pragma unroll
    for (int o = 16; o; o >>= 1) v = fmaxf(v, __shfl_xor_sync(0xffffffffu, v, o));
    return v;
}
__device__ __forceinline__ float dot8(float4 w1, float4 w2, float4 h1, float4 h2) {
    return w1.x*h1.x + w1.y*h1.y + w1.z*h1.z + w1.w*h1.w
         + w2.x*h2.x + w2.y*h2.y + w2.z*h2.z + w2.w*h2.w;
}

// ================= K_tr: tiled transposes (once) =================
__global__ __launch_bounds__(256, 4)
void k_tr(const float* __restrict__ Wh, const float* __restrict__ Wq,
          const float* __restrict__ Wch, const float* __restrict__ Wm,
          const float* __restrict__ addr)
{
    __shared__ float tile[32][33];
    int blk = blockIdx.x, tid = threadIdx.x;
    const float* src; float* dst; int C, R, tr, tc;
    if (blk < 192)      { src = Wh;  dst = g_WhT;  R = 768;  C = 256; int i = blk;       tr = i >> 3; tc = i & 7; }
    else if (blk < 384) { src = Wm;  dst = g_WmT;  R = 768;  C = 256; int i = blk - 192; tr = i >> 3; tc = i & 7; }
    else if (blk < 448) { src = Wq;  dst = g_WqT;  R = 256;  C = 256; int i = blk - 384; tr = i >> 3; tc = i & 7; }
    else if (blk < 496) { src = Wch; dst = g_WchT; R = 192;  C = 256; int i = blk - 448; tr = i >> 3; tc = i & 7; }
    else                { src = addr;dst = g_addrT;R = 1024; C = 64;  int i = blk - 496; tr = i >> 1; tc = i & 1; }
    int r0 = tr*32, c0 = tc*32, rr = tid >> 5, cc = tid & 31;
    #pragma unroll
    for (int p = 0; p < 4; p++)
        tile[rr + p*8][cc] = src[(r0 + rr + p*8)*C + c0 + cc];
    __syncthreads();
    #pragma unroll
    for (int p = 0; p < 4; p++)
        dst[(c0 + rr + p*8)*R + r0 + cc] = tile[cc][rr + p*8];
}

// ================= K0: gi / cx precompute (once) =================
__global__ __launch_bounds__(256, 4)
void k_init(const float* __restrict__ batch,
            const float* __restrict__ Wi, const float* __restrict__ bi,
            const float* __restrict__ Wci)
{
    int blk = blockIdx.x, tid = threadIdx.x, lane = tid & 31, wl = tid >> 5;
    int t = blk >> 5, b = blk & 31;
    __shared__ float sx[64];
    if (tid < 64) {
        int idx = tid*32 + b;          // raw-reshape: x_t[f,b] = flat[f*32+b]
        sx[tid] = batch[(idx >> 6)*(T_*F_) + t*F_ + (idx & 63)];
    }
    __syncthreads();
    for (int r = wl; r < 960; r += 8) {
        if (r < 768) {
            float acc = Wi[r*64 + lane]*sx[lane] + Wi[r*64 + 32 + lane]*sx[32 + lane];
            acc = warp_sum(acc);
            if (lane == 0) g_giA[(t*32 + b)*768 + r] = acc + bi[r];
        } else {
            int c = r - 768;
            float acc = Wci[c*64 + lane]*sx[lane] + Wci[c*64 + 32 + lane]*sx[32 + lane];
            acc = warp_sum(acc);
            if (lane == 0) g_cxA[(t*32 + b)*192 + c] = acc;
        }
    }
}

// ================= smem layout (floats); [bl] = which of 2 b's =================
#define SM_W     0          // 16384  w[bl][s][nl] : bl*8192 + s*256 + nl
#define SM_ADDR  16384      // 16384  addrT quarter [a*256+nl] (shared by both b)
#define SM_CAND  32768      // 12288  cand[bl][s][c] : bl*6144 + s*192 + c
#define SM_GI    45056      // 384    gi[bl][j] : bl*192 + j  (j = g*64+jj)
#define SM_GHP   45440      // 3072   ghp[bl][kq][j] : bl*1536 + kq*192 + j
#define SM_GMP   48512      // 3072   gmp same  (SIMP aliases first 2048)
#define SM_QP    51584      // 512    qp[bl][kq][j] : bl*256 + kq*64 + j
#define SM_CP    52096      // 384    cp[bl][kq][j] : bl*192 + kq*48 + j
#define SM_Q     52480      // 512    q[bl][m]
#define SM_H     52992      // 512    h[bl][k]
#define SM_R     53504      // 512    r[bl][m]
#define SM_GP    54016      // 256    Gp[bl][r][s] : bl*128 + r*32 + s
#define SM_RAP   54272      // 512    rap[bl][r][a] : bl*256 + r*64 + a
#define SM_STAT  54784      // 16     stat[bl][r][2] : bl*8 + r*2
#define SM_BH    54800      // 192
#define SM_BM    54992      // 192
#define SM_BQ    55184      // 64
#define SM_U     55248      // 256
#define SM_BO    55504      // 16
#define SM_D     55520      // 64     d[bl][s]
#define SM_G     55584      // 64     G[bl][s]
#define SM_MX    55648      // 16     mx[wl 0..15]
#define SM_E     55664      // 16
#define SM_BETA  55680      // 2
#define SMEM_FLOATS 55696
#define SM_SIMP  SM_GMP     // simp[bl][half][nl] : bl*512 + half*256 + nl

__global__ __launch_bounds__(1024, 1) __cluster_dims__(4, 1, 1)
void k_run(const float* __restrict__ bh,  const float* __restrict__ bq,
           const float* __restrict__ uvec,const float* __restrict__ bm,
           const float* __restrict__ Wout,const float* __restrict__ bo,
           float* __restrict__ out)
{
    extern __shared__ __align__(16) float sm[];
    float* s_w    = sm + SM_W;
    float* s_addr = sm + SM_ADDR;
    float* s_cand = sm + SM_CAND;
    float* s_gi   = sm + SM_GI;
    float* s_ghp  = sm + SM_GHP;
    float* s_gmp  = sm + SM_GMP;
    float* s_simp = sm + SM_SIMP;
    float* s_qp   = sm + SM_QP;
    float* s_cp   = sm + SM_CP;
    float* s_q    = sm + SM_Q;
    float* s_h    = sm + SM_H;
    float* s_r    = sm + SM_R;
    float* s_Gp   = sm + SM_GP;
    float* s_rap  = sm + SM_RAP;
    float* s_stat = sm + SM_STAT;
    float* s_bh   = sm + SM_BH;
    float* s_bm   = sm + SM_BM;
    float* s_bq   = sm + SM_BQ;
    float* s_u    = sm + SM_U;
    float* s_bo   = sm + SM_BO;
    float* s_d    = sm + SM_D;
    float* s_G    = sm + SM_G;
    float* s_mx   = sm + SM_MX;
    float* s_e    = sm + SM_E;
    float* s_beta = sm + SM_BETA;

    cg::cluster_group cl = cg::this_cluster();
    const unsigned rank = cl.block_rank();
    float* peer[3];
    #pragma unroll
    for (int i = 0; i < 3; i++)
        peer[i] = (float*)cl.map_shared_rank((void*)sm, (rank + 1 + i) & 3);

    const int b0 = (blockIdx.x >> 2) * 2;       // 16 clusters x 2 b's
    const int r = (int)rank;
    const int tid = threadIdx.x, lane = tid & 31, wl = tid >> 5;

    // ---- one-time staging ----
    if (tid < 192) {
        int g = tid >> 6, j = tid & 63;
        s_bh[tid] = bh[g*256 + r*64 + j];
        s_bm[tid] = bm[g*256 + r*64 + j];
    }
    if (tid < 64) s_bq[tid] = bq[r*64 + tid];
    if (tid < 256) s_u[tid] = uvec[tid];
    if (tid < 512) s_h[tid] = 0.f;
    if (tid < 10) s_bo[tid] = bo[tid];
    for (int i = tid; i < A_*256; i += 1024) {
        int a = i >> 8, nl = i & 255;
        s_addr[i] = g_addrT[a*N_ + r*256 + nl];
    }
    cl.sync();

    for (int t = 0; t < T_; t++) {
        // ===== S1: gh(24w) + q(4w) + cand(4w), both b's per weight load =====
        if (wl < 24) {
            int g = wl >> 3, kq = wl & 7;
            int jl = g*64 + lane*2;                 // local row (0..191)
            int grow = g*256 + r*64 + lane*2;       // global row
            int k0 = kq << 5;
            float a00 = 0.f, a01 = 0.f, a10 = 0.f, a11 = 0.f;
            #pragma unroll 8
            for (int k = k0; k < k0 + 32; k++) {
                float2 w = *(const float2*)(g_WhT + k*768 + grow);
                float h0 = s_h[k], h1 = s_h[256 + k];
                a00 += w.x*h0; a01 += w.y*h0;
                a10 += w.x*h1; a11 += w.y*h1;
            }
            s_ghp[kq*192 + jl    ] = a00;
            s_ghp[kq*192 + jl + 1] = a01;
            s_ghp[1536 + kq*192 + jl    ] = a10;
            s_ghp[1536 + kq*192 + jl + 1] = a11;
        } else if (wl < 28) {
            int kq = wl - 24, k0 = kq << 6;
            int jl = lane*2;
            int gm = r*64 + lane*2;
            float a00 = 0.f, a01 = 0.f, a10 = 0.f, a11 = 0.f;
            #pragma unroll 8
            for (int k = k0; k < k0 + 64; k++) {
                float2 w = *(const float2*)(g_WqT + k*256 + gm);
                float h0 = s_h[k], h1 = s_h[256 + k];
                a00 += w.x*h0; a01 += w.y*h0;
                a10 += w.x*h1; a11 += w.y*h1;
            }
            s_qp[kq*64 + jl    ] = a00;
            s_qp[kq*64 + jl + 1] = a01;
            s_qp[256 + kq*64 + jl    ] = a10;
            s_qp[256 + kq*64 + jl + 1] = a11;
        } else {
            int kq = wl - 28, k0 = kq << 6;
            if (lane < 24) {
                int jl = lane*2;
                int gc = r*48 + lane*2;
                float a00 = 0.f, a01 = 0.f, a10 = 0.f, a11 = 0.f;
                #pragma unroll 8
                for (int k = k0; k < k0 + 64; k++) {
                    float2 w = *(const float2*)(g_WchT + k*192 + gc);
                    float h0 = s_h[k], h1 = s_h[256 + k];
                    a00 += w.x*h0; a01 += w.y*h0;
                    a10 += w.x*h1; a11 += w.y*h1;
                }
                s_cp[kq*48 + jl    ] = a00;
                s_cp[kq*48 + jl + 1] = a01;
                s_cp[192 + kq*48 + jl    ] = a10;
                s_cp[192 + kq*48 + jl + 1] = a11;
            }
        }
        __syncthreads();

        // ===== S2: combines + broadcasts, gi load, beta, head(t-1) =====
        if (tid < 128) {
            int bl = tid >> 6, j = tid & 63;
            const float* qp = s_qp + bl*256;
            float v = qp[j] + qp[64 + j] + qp[128 + j] + qp[192 + j] + s_bq[j];
            int off = SM_Q + bl*256 + r*64 + j;
            sm[off] = v;
            peer[0][off] = v; peer[1][off] = v; peer[2][off] = v;
        } else if (tid < 224) {
            int idx = tid - 128;
            int bl = idx / 48, j = idx % 48;
            const float* cp = s_cp + bl*192;
            float v = cp[j] + cp[48 + j] + cp[96 + j] + cp[144 + j]
                    + g_cxA[(t*32 + b0 + bl)*192 + r*48 + j];
            v = fmaxf(v, 0.f);
            int off = SM_CAND + bl*6144 + t*192 + r*48 + j;
            sm[off] = v;
            peer[0][off] = v; peer[1][off] = v; peer[2][off] = v;
        } else if (tid >= 256 && tid < 640) {
            int idx = tid - 256;
            int bl = idx / 192, j = idx % 192;
            int g = j >> 6, jj = j & 63;
            s_gi[bl*192 + j] = g_giA[(t*32 + b0 + bl)*768 + g*256 + r*64 + jj];
        } else if ((wl == 24 || wl == 25) && rank == 0) {
            int bl = wl - 24;
            const float4* u4 = (const float4*)s_u;
            const float4* hb4 = (const float4*)(s_h + bl*256);
            float acc = dot8(u4[lane], u4[32 + lane], hb4[lane], hb4[32 + lane]);
            acc = warp_sum(acc);
            if (lane == 0) {
                float sp = (acc > 0.f) ? acc + log1pf(expf(-acc)) : log1pf(expf(acc));
                float bv = sp + 1.f;
                sm[SM_BETA + bl] = bv;
                peer[0][SM_BETA + bl] = bv; peer[1][SM_BETA + bl] = bv;
                peer[2][SM_BETA + bl] = bv;
            }
        } else if ((wl == 26 || wl == 27) && rank == 0 && t > 0) {
            int bl = wl - 26;
            const float* hb = s_h + bl*256;
            float logit[10];
            float mx = -1e30f;
            #pragma unroll
            for (int o = 0; o < 10; o++) {
                float s = 0.f;
                #pragma unroll
                for (int j = 0; j < 8; j++) {
                    int k = lane + 32*j;
                    s += Wout[o*H_ + k] * hb[k];
                }
                s = warp_sum(s);
                s += s_bo[o];
                logit[o] = s;
                mx = fmaxf(mx, s);
            }
            float se = 0.f;
            #pragma unroll
            for (int o = 0; o < 10; o++) se += expf(logit[o] - mx);
            float lse = mx + logf(se);
            if (lane == 0) {
                #pragma unroll
                for (int o = 0; o < 10; o++)
                    out[HSOFF + ((t-1)*10 + o)*B_ + b0 + bl] = logit[o] - lse;
            }
        }
        cl.sync();                              // q, cand, beta visible

        // ===== S3: d_s for both b's (warp per (s,bl)) =====
        for (int idx = wl; idx < 2*t; idx += 32) {
            int s = idx >> 1, bl = idx & 1;
            const float* cr = s_cand + bl*6144 + s*192;
            const float* qc = s_q + bl*256 + A_;
            float acc = 0.f;
            #pragma unroll
            for (int j = 0; j < 6; j++) {
                int c = lane + 32*j;
                acc += cr[c] * qc[c];
            }
            acc = warp_sum(acc);
            if (lane == 0) s_d[bl*32 + s] = acc;
        }
        __syncthreads();

        // ===== S4: sim partials (1024 thr: bl x half x 256n) + cluster softmax =====
        {
            int nl = tid & 255, half = (tid >> 8) & 1, bl = tid >> 9;
            const float* qb = s_q + bl*256;
            float acc = 0.f;
            int a0 = half << 5;
            #pragma unroll
            for (int a = a0; a < a0 + 32; a++)
                acc += qb[a] * s_addr[a*256 + nl];
            const float* wb = s_w + bl*8192;
            const float* db = s_d + bl*32;
            for (int s = half; s < t; s += 2)
                acc += wb[s*256 + nl] * db[s];
            s_simp[bl*512 + half*256 + nl] = acc;
        }
        __syncthreads();
        float v = 0.f, e_reg = 0.f, mloc = 0.f;
        int bl4 = tid >> 8;                      // valid for tid < 512
        if (tid < 512) {
            int nl = tid & 255;
            v = sm[SM_BETA + bl4] * (s_simp[bl4*512 + nl] + s_simp[bl4*512 + 256 + nl]);
            float mx = warp_max(v);
            if (lane == 0) s_mx[wl] = mx;        // warps 0-7 = b0, 8-15 = b1
        }
        __syncthreads();
        if (tid < 512) {
            mloc = s_mx[bl4*8];
            #pragma unroll
            for (int w = 1; w < 8; w++) mloc = fmaxf(mloc, s_mx[bl4*8 + w]);
            e_reg = expf(v - mloc);
            float es = warp_sum(e_reg);
            if (lane == 0) s_e[wl] = es;
        }
        __syncthreads();
        if (tid == 0 || tid == 256) {
            int bl = tid >> 8;
            float sl = 0.f;
            #pragma unroll
            for (int w = 0; w < 8; w++) sl += s_e[bl*8 + w];
            int off = SM_STAT + bl*8 + r*2;
            sm[off] = mloc; sm[off + 1] = sl;
            #pragma unroll
            for (int i = 0; i < 3; i++) {
                peer[i][off] = mloc; peer[i][off + 1] = sl;
            }
        }
        cl.sync();                              // stats visible
        if (tid < 512) {
            const float* st = s_stat + bl4*8;
            float M = fmaxf(fmaxf(st[0], st[2]), fmaxf(st[4], st[6]));
            float S = st[1]*expf(st[0] - M) + st[3]*expf(st[2] - M)
                    + st[5]*expf(st[4] - M) + st[7]*expf(st[6] - M);
            s_w[bl4*8192 + t*256 + (tid & 255)] = e_reg * expf(mloc - M) / S;
        }
        __syncthreads();

        // ===== S5: G (warp per (s,bl)) + ra (warp per (bl, 4 a's)), smem =====
        for (int idx = wl; idx < 2*t; idx += 32) {
            int s = idx >> 1, bl = idx & 1;
            const float4* wsp = (const float4*)(s_w + bl*8192 + s*256);
            const float4* wtp = (const float4*)(s_w + bl*8192 + t*256);
            float4 a0 = wsp[lane], c0 = wtp[lane];
            float4 a1 = wsp[32 + lane], c1 = wtp[32 + lane];
            float g = a0.x*c0.x + a0.y*c0.y + a0.z*c0.z + a0.w*c0.w
                    + a1.x*c1.x + a1.y*c1.y + a1.z*c1.z + a1.w*c1.w;
            g = warp_sum(g);
            if (lane == 0) {
                int off = SM_GP + bl*128 + r*32 + s;
                sm[off] = g;
                peer[0][off] = g; peer[1][off] = g; peer[2][off] = g;
            }
        }
        {
            int bl = wl >> 4, aq = wl & 15;
            const float* wt = s_w + bl*8192 + t*256;
            float acc[4] = {0.f, 0.f, 0.f, 0.f};
            #pragma unroll
            for (int p = 0; p < 4; p++) {
                const float* at = s_addr + (aq*4 + p)*256;
                float a = 0.f;
                #pragma unroll
                for (int j = 0; j < 8; j++) {
                    int nn = lane + 32*j;
                    a += wt[nn] * at[nn];
                }
                acc[p] = warp_sum(a);
            }
            if (lane == 0) {
                #pragma unroll
                for (int p = 0; p < 4; p++) {
                    int off = SM_RAP + bl*256 + r*64 + aq*4 + p;
                    sm[off] = acc[p];
                    peer[0][off] = acc[p]; peer[1][off] = acc[p]; peer[2][off] = acc[p];
                }
            }
        }
        cl.sync();                              // G/ra partials visible

        // ===== S6: combine G + ra, then rc =====
        if (tid < 64) {
            int bl = tid >> 5, s = tid & 31;
            const float* gp = s_Gp + bl*128;
            s_G[bl*32 + s] = gp[s] + gp[32 + s] + gp[64 + s] + gp[96 + s];
        } else if (tid < 192) {
            int idx = tid - 64;
            int bl = idx >> 6, a = idx & 63;
            const float* rp = s_rap + bl*256;
            s_r[bl*256 + a] = rp[a] + rp[64 + a] + rp[128 + a] + rp[192 + a];
        }
        __syncthreads();
        if (tid >= 256 && tid < 640) {
            int idx = tid - 256;
            int bl = idx / 192, c = idx % 192;
            const float* gb = s_G + bl*32;
            const float* cb = s_cand + bl*6144;
            float acc = 0.f;
            for (int s = 0; s < t; s++)
                acc += gb[s] * cb[s*192 + c];
            s_r[bl*256 + A_ + c] = acc;
        }
        __syncthreads();

        // ===== S7: gm partials (24 warps, both b's per weight load) =====
        if (wl < 24) {
            int g = wl >> 3, kq = wl & 7;
            int jl = g*64 + lane*2;
            int grow = g*256 + r*64 + lane*2;
            int m0 = kq << 5;
            float a00 = 0.f, a01 = 0.f, a10 = 0.f, a11 = 0.f;
            #pragma unroll 8
            for (int m = m0; m < m0 + 32; m++) {
                float2 w = *(const float2*)(g_WmT + m*768 + grow);
                float r0 = s_r[m], r1 = s_r[256 + m];
                a00 += w.x*r0; a01 += w.y*r0;
                a10 += w.x*r1; a11 += w.y*r1;
            }
            s_gmp[kq*192 + jl    ] = a00;
            s_gmp[kq*192 + jl + 1] = a01;
            s_gmp[1536 + kq*192 + jl    ] = a10;
            s_gmp[1536 + kq*192 + jl + 1] = a11;
        }
        __syncthreads();

        // ===== S8: gate combine + h slice update + broadcast =====
        if (tid < 128) {
            int bl = tid >> 6, j = tid & 63;
            int hid = r*64 + j;
            const float* ghp = s_ghp + bl*1536;
            const float* gmp = s_gmp + bl*1536;
            float gh0 = s_bh[j],       gm0 = s_bm[j];
            float gh1 = s_bh[64 + j],  gm1 = s_bm[64 + j];
            float gh2 = s_bh[128 + j], gm2 = s_bm[128 + j];
            #pragma unroll
            for (int kq = 0; kq < 8; kq++) {
                gh0 += ghp[kq*192 + j];
                gh1 += ghp[kq*192 + 64 + j];
                gh2 += ghp[kq*192 + 128 + j];
                gm0 += gmp[kq*192 + j];
                gm1 += gmp[kq*192 + 64 + j];
                gm2 += gmp[kq*192 + 128 + j];
            }
            const float* gib = s_gi + bl*192;
            float rr = 1.f / (1.f + expf(-(gib[j] + gh0 + gm0)));
            float zz = 1.f / (1.f + expf(-(gib[64 + j] + gh1 + gm1)));
            float nn = tanhf(gib[128 + j] + gm2 + rr*gh2);
            float hn = (1.f - zz)*nn + zz*s_h[bl*256 + hid];
            int off = SM_H + bl*256 + hid;
            sm[off] = hn;
            peer[0][off] = hn; peer[1][off] = hn; peer[2][off] = hn;
            out[t*H_*B_ + hid*32 + b0 + bl] = hn;
        }
        cl.sync();                              // full h visible
    }

    // final head (t = T-1), rank 0, warps 0/1
    if (rank == 0 && wl < 2) {
        int bl = wl;
        const float* hb = s_h + bl*256;
        float logit[10];
        float mx = -1e30f;
        #pragma unroll
        for (int o = 0; o < 10; o++) {
            float s = 0.f;
            #pragma unroll
            for (int j = 0; j < 8; j++) {
                int k = lane + 32*j;
                s += Wout[o*H_ + k] * hb[k];
            }
            s = warp_sum(s);
            s += s_bo[o];
            logit[o] = s;
            mx = fmaxf(mx, s);
        }
        float se = 0.f;
        #pragma unroll
        for (int o = 0; o < 10; o++) se += expf(logit[o] - mx);
        float lse = mx + logf(se);
        if (lane == 0) {
            #pragma unroll
            for (int o = 0; o < 10; o++)
                out[HSOFF + ((T_-1)*10 + o)*B_ + b0 + bl] = logit[o] - lse;
        }
    }
}

extern "C" void kernel_launch(void* const* d_in, const int* in_sizes, int n_in,
                              void* d_out, int out_size) {
    (void)in_sizes; (void)n_in; (void)out_size;
    const float* batch = (const float*)d_in[0];
    const float* Wi    = (const float*)d_in[1];
    const float* bi    = (const float*)d_in[2];
    const float* Wh    = (const float*)d_in[3];
    const float* bh    = (const float*)d_in[4];
    const float* Wm    = (const float*)d_in[5];
    const float* bm    = (const float*)d_in[6];
    const float* Wout  = (const float*)d_in[7];
    const float* bo    = (const float*)d_in[8];
    const float* addr  = (const float*)d_in[9];
    const float* Wq    = (const float*)d_in[10];
    const float* bq    = (const float*)d_in[11];
    const float* u     = (const float*)d_in[12];
    const float* Wch   = (const float*)d_in[13];
    const float* Wci   = (const float*)d_in[14];
    float* out = (float*)d_out;

    static int smem_set = 0;
    if (!smem_set) {
        cudaFuncSetAttribute((const void*)k_run,
                             cudaFuncAttributeMaxDynamicSharedMemorySize,
                             SMEM_FLOATS * 4);
        smem_set = 1;
    }
    k_tr<<<560, 256>>>(Wh, Wq, Wch, Wm, addr);
    k_init<<<1024, 256>>>(batch, Wi, bi, Wci);
    k_run<<<64, 1024, SMEM_FLOATS * 4>>>(bh, bq, u, bm, Wout, bo, out);
}

// round 17
// speedup vs baseline: 1.3476x; 1.3476x over previous
#include <cuda_runtime.h>
#include <cooperative_groups.h>
#include <math.h>

namespace cg = cooperative_groups;

#define B_ 32
#define T_ 32
#define F_ 64
#define H_ 256
#define N_ 1024
#define A_ 64
#define C_ 192
#define M_ 256
#define HSOFF (T_*H_*B_)

// ---------------- precomputed globals ----------------
__device__ __align__(16) float g_addrT[A_*N_];     // addrT[a*1024+n]
__device__ __align__(16) float g_giA[T_*B_*768];   // gi: [(t*32+b)*768+row]
__device__ __align__(16) float g_cxA[T_*B_*C_];    // Wci@x: [(t*32+b)*192+c]
__device__ __align__(16) float g_WhT[H_*768];      // [k*768+row]
__device__ __align__(16) float g_WqT[H_*M_];       // [k*256+m]
__device__ __align__(16) float g_WchT[H_*C_];      // [k*192+c]
__device__ __align__(16) float g_WmT[M_*768];      // [m*768+row]

__device__ __forceinline__ float warp_sum(float v) {
    #pragma unroll
    for (int o = 16; o; o >>= 1) v += __shfl_xor_sync(0xffffffffu, v, o);
    return v;
}
__device__ __forceinline__ float warp_max(float v) {
    #pragma unroll
    for (int o = 16; o; o >>= 1) v = fmaxf(v, __shfl_xor_sync(0xffffffffu, v, o));
    return v;
}
__device__ __forceinline__ float dot8(float4 w1, float4 w2, float4 h1, float4 h2) {
    return w1.x*h1.x + w1.y*h1.y + w1.z*h1.z + w1.w*h1.w
         + w2.x*h2.x + w2.y*h2.y + w2.z*h2.z + w2.w*h2.w;
}

// ================= K_tr: tiled transposes (once) =================
__global__ __launch_bounds__(256, 4)
void k_tr(const float* __restrict__ Wh, const float* __restrict__ Wq,
          const float* __restrict__ Wch, const float* __restrict__ Wm,
          const float* __restrict__ addr)
{
    __shared__ float tile[32][33];
    int blk = blockIdx.x, tid = threadIdx.x;
    const float* src; float* dst; int C, R, tr, tc;
    if (blk < 192)      { src = Wh;  dst = g_WhT;  R = 768;  C = 256; int i = blk;       tr = i >> 3; tc = i & 7; }
    else if (blk < 384) { src = Wm;  dst = g_WmT;  R = 768;  C = 256; int i = blk - 192; tr = i >> 3; tc = i & 7; }
    else if (blk < 448) { src = Wq;  dst = g_WqT;  R = 256;  C = 256; int i = blk - 384; tr = i >> 3; tc = i & 7; }
    else if (blk < 496) { src = Wch; dst = g_WchT; R = 192;  C = 256; int i = blk - 448; tr = i >> 3; tc = i & 7; }
    else                { src = addr;dst = g_addrT;R = 1024; C = 64;  int i = blk - 496; tr = i >> 1; tc = i & 1; }
    int r0 = tr*32, c0 = tc*32, rr = tid >> 5, cc = tid & 31;
    #pragma unroll
    for (int p = 0; p < 4; p++)
        tile[rr + p*8][cc] = src[(r0 + rr + p*8)*C + c0 + cc];
    __syncthreads();
    #pragma unroll
    for (int p = 0; p < 4; p++)
        dst[(c0 + rr + p*8)*R + r0 + cc] = tile[cc][rr + p*8];
}

// ================= K0: gi / cx precompute (once) =================
__global__ __launch_bounds__(256, 4)
void k_init(const float* __restrict__ batch,
            const float* __restrict__ Wi, const float* __restrict__ bi,
            const float* __restrict__ Wci)
{
    int blk = blockIdx.x, tid = threadIdx.x, lane = tid & 31, wl = tid >> 5;
    int t = blk >> 5, b = blk & 31;
    __shared__ float sx[64];
    if (tid < 64) {
        int idx = tid*32 + b;          // raw-reshape: x_t[f,b] = flat[f*32+b]
        sx[tid] = batch[(idx >> 6)*(T_*F_) + t*F_ + (idx & 63)];
    }
    __syncthreads();
    for (int r = wl; r < 960; r += 8) {
        if (r < 768) {
            float acc = Wi[r*64 + lane]*sx[lane] + Wi[r*64 + 32 + lane]*sx[32 + lane];
            acc = warp_sum(acc);
            if (lane == 0) g_giA[(t*32 + b)*768 + r] = acc + bi[r];
        } else {
            int c = r - 768;
            float acc = Wci[c*64 + lane]*sx[lane] + Wci[c*64 + 32 + lane]*sx[32 + lane];
            acc = warp_sum(acc);
            if (lane == 0) g_cxA[(t*32 + b)*192 + c] = acc;
        }
    }
}

// ================= smem layout (floats) =================
#define SM_W     0          // 8192   u-hist[32][256] (own n-quarter, raw exp)
#define SM_ADDR  8192       // 16384  addrT quarter [a*256+nl]
#define SM_CAND  24576      // 6144   cand[32][192] (full via exchange)
#define SM_GI    30720      // 192
#define SM_GHP   30912      // 1536
#define SM_GMP   32448      // 1536   (SIMP aliases)
#define SM_QP    33984      // 256
#define SM_CP    34240      // 192
#define SM_Q     34432      // 256
#define SM_H     34688      // 256
#define SM_R     34944      // 256
#define SM_SIMP  SM_GMP     // 1024   sim partials (4 grp x 256)
#define SM_GP    36224      // 128
#define SM_RAP   36352      // 256
#define SM_STAT  36608      // 8
#define SM_SHIST 36616      // 128    f factors [r'][s]
#define SM_BH    36744      // 192
#define SM_BM    36936      // 192
#define SM_BQ    37128      // 64
#define SM_U     37192      // 256
#define SM_WOUT  37448      // 2560
#define SM_BO    40008      // 16
#define SM_D     40024      // 32
#define SM_G     40056      // 32
#define SM_MX    40088      // 8
#define SM_E     40096      // 8
#define SM_BETA  40104      // 4
#define SMEM_FLOATS 40112

__global__ __launch_bounds__(1024, 1) __cluster_dims__(4, 1, 1)
void k_run(const float* __restrict__ bh,  const float* __restrict__ bq,
           const float* __restrict__ uvec,const float* __restrict__ bm,
           const float* __restrict__ Wout,const float* __restrict__ bo,
           float* __restrict__ out)
{
    extern __shared__ __align__(16) float sm[];
    float* s_w    = sm + SM_W;
    float* s_addr = sm + SM_ADDR;
    float* s_cand = sm + SM_CAND;
    float* s_gi   = sm + SM_GI;
    float* s_ghp  = sm + SM_GHP;
    float* s_gmp  = sm + SM_GMP;
    float* s_simp = sm + SM_SIMP;
    float* s_qp   = sm + SM_QP;
    float* s_cp   = sm + SM_CP;
    float* s_q    = sm + SM_Q;
    float* s_h    = sm + SM_H;
    float* s_r    = sm + SM_R;
    float* s_Gp   = sm + SM_GP;
    float* s_rap  = sm + SM_RAP;
    float* s_stat = sm + SM_STAT;
    float* s_shist= sm + SM_SHIST;
    float* s_bh   = sm + SM_BH;
    float* s_bm   = sm + SM_BM;
    float* s_bq   = sm + SM_BQ;
    float* s_u    = sm + SM_U;
    float* s_Wout = sm + SM_WOUT;
    float* s_bo   = sm + SM_BO;
    float* s_d    = sm + SM_D;
    float* s_G    = sm + SM_G;
    float* s_mx   = sm + SM_MX;
    float* s_e    = sm + SM_E;
    float* s_beta = sm + SM_BETA;

    cg::cluster_group cl = cg::this_cluster();
    const unsigned rank = cl.block_rank();
    float* peer[3];
    #pragma unroll
    for (int i = 0; i < 3; i++)
        peer[i] = (float*)cl.map_shared_rank((void*)sm, (rank + 1 + i) & 3);

    const int b = blockIdx.x >> 2;
    const int r = (int)rank;
    const int tid = threadIdx.x, lane = tid & 31, wl = tid >> 5;
    const float4* h4 = (const float4*)s_h;

    // ---- one-time staging ----
    if (tid < 192) {
        int g = tid >> 6, j = tid & 63;
        s_bh[tid] = bh[g*256 + r*64 + j];
        s_bm[tid] = bm[g*256 + r*64 + j];
    }
    if (tid < 64) s_bq[tid] = bq[r*64 + tid];
    if (tid < 256) { s_u[tid] = uvec[tid]; s_h[tid] = 0.f; }
    for (int i = tid; i < 2560; i += 1024) s_Wout[i] = Wout[i];
    if (tid < 10) s_bo[tid] = bo[tid];
    for (int i = tid; i < A_*256; i += 1024) {
        int a = i >> 8, nl = i & 255;
        s_addr[i] = g_addrT[a*N_ + r*256 + nl];
    }
    cl.sync();

    for (int t = 0; t < T_; t++) {
        // ===== S1: gh(24w) + q(4w) + cand(4w) partials — r's row quarters =====
        if (wl < 24) {
            int g = wl >> 3, kq = wl & 7;
            int row = g*256 + r*64 + lane*2;
            int k0 = kq << 5;
            float a0 = 0.f, a1 = 0.f;
            #pragma unroll 8
            for (int k = k0; k < k0 + 32; k++) {
                float2 w = *(const float2*)(g_WhT + k*768 + row);
                float hk = s_h[k];
                a0 += w.x*hk; a1 += w.y*hk;
            }
            s_ghp[kq*192 + g*64 + lane*2    ] = a0;
            s_ghp[kq*192 + g*64 + lane*2 + 1] = a1;
        } else if (wl < 28) {
            int kq = wl - 24, k0 = kq << 6;
            int m0 = r*64 + lane*2;
            float a0 = 0.f, a1 = 0.f;
            #pragma unroll 8
            for (int k = k0; k < k0 + 64; k++) {
                float2 w = *(const float2*)(g_WqT + k*256 + m0);
                float hk = s_h[k];
                a0 += w.x*hk; a1 += w.y*hk;
            }
            s_qp[kq*64 + lane*2    ] = a0;
            s_qp[kq*64 + lane*2 + 1] = a1;
        } else {
            int kq = wl - 28, k0 = kq << 6;
            if (lane < 24) {
                int c0 = r*48 + lane*2;
                float a0 = 0.f, a1 = 0.f;
                #pragma unroll 8
                for (int k = k0; k < k0 + 64; k++) {
                    float2 w = *(const float2*)(g_WchT + k*192 + c0);
                    float hk = s_h[k];
                    a0 += w.x*hk; a1 += w.y*hk;
                }
                s_cp[kq*48 + lane*2    ] = a0;
                s_cp[kq*48 + lane*2 + 1] = a1;
            }
        }
        __syncthreads();

        // ===== S2: combines + broadcasts, gi load, beta, head(t-1) =====
        if (tid < 64) {
            float v = s_qp[tid] + s_qp[64 + tid] + s_qp[128 + tid] + s_qp[192 + tid]
                    + s_bq[tid];
            int off = SM_Q + r*64 + tid;
            s_q[r*64 + tid] = v;
            peer[0][off] = v; peer[1][off] = v; peer[2][off] = v;
        } else if (tid < 112) {
            int j = tid - 64;
            float v = s_cp[j] + s_cp[48 + j] + s_cp[96 + j] + s_cp[144 + j]
                    + g_cxA[(t*32 + b)*192 + r*48 + j];
            v = fmaxf(v, 0.f);
            int off = SM_CAND + t*192 + r*48 + j;
            s_cand[t*192 + r*48 + j] = v;
            peer[0][off] = v; peer[1][off] = v; peer[2][off] = v;
        } else if (tid >= 128 && tid < 320) {
            int j = tid - 128;
            int g = j >> 6, jj = j & 63;
            s_gi[j] = g_giA[(t*32 + b)*768 + g*256 + r*64 + jj];
        } else if (wl == 12 && rank == 0) {
            const float4* u4 = (const float4*)s_u;
            float acc = dot8(u4[lane], u4[32 + lane], h4[lane], h4[32 + lane]);
            acc = warp_sum(acc);
            if (lane == 0) {
                float sp = (acc > 0.f) ? acc + log1pf(expf(-acc)) : log1pf(expf(acc));
                float bv = sp + 1.f;
                s_beta[0] = bv;
                peer[0][SM_BETA] = bv; peer[1][SM_BETA] = bv; peer[2][SM_BETA] = bv;
            }
        } else if (wl == 13 && rank == 0 && t > 0) {
            float logit[10];
            float mx = -1e30f;
            #pragma unroll
            for (int o = 0; o < 10; o++) {
                float s = 0.f;
                #pragma unroll
                for (int j = 0; j < 8; j++) {
                    int k = lane + 32*j;
                    s += s_Wout[o*H_ + k] * s_h[k];
                }
                s = warp_sum(s);
                s += s_bo[o];
                logit[o] = s;
                mx = fmaxf(mx, s);
            }
            float se = 0.f;
            #pragma unroll
            for (int o = 0; o < 10; o++) se += expf(logit[o] - mx);
            float lse = mx + logf(se);
            if (lane == 0) {
                #pragma unroll
                for (int o = 0; o < 10; o++)
                    out[HSOFF + ((t-1)*10 + o)*B_ + b] = logit[o] - lse;
            }
        }
        cl.sync();                              // [A] q, cand, beta visible

        // ===== S3: d_s (warp per s < t), folded with f_{s,rank} =====
        if (wl < t) {
            float acc = 0.f;
            #pragma unroll
            for (int j = 0; j < 6; j++) {
                int c = lane + 32*j;
                acc += s_cand[wl*192 + c] * s_q[A_ + c];
            }
            acc = warp_sum(acc);
            if (lane == 0) s_d[wl] = acc * s_shist[r*32 + wl];
        }
        __syncthreads();

        // ===== S4: sim partials + LOCAL softmax (raw u stored), stats pushed =====
        {
            int nl = tid & 255, grp = tid >> 8;
            float acc = 0.f;
            int a0 = grp << 4;
            #pragma unroll
            for (int a = a0; a < a0 + 16; a++)
                acc += s_q[a] * s_addr[a*256 + nl];
            for (int s = grp; s < t; s += 4)
                acc += s_w[s*256 + nl] * s_d[s];
            s_simp[grp*256 + nl] = acc;
        }
        __syncthreads();
        float v = 0.f, e_reg = 0.f, mloc = 0.f;
        if (tid < 256) {
            v = s_beta[0] * (s_simp[tid] + s_simp[256 + tid]
                           + s_simp[512 + tid] + s_simp[768 + tid]);
            float mx = warp_max(v);
            if (lane == 0) s_mx[wl] = mx;
        }
        __syncthreads();
        if (tid < 256) {
            mloc = s_mx[0];
            #pragma unroll
            for (int w = 1; w < 8; w++) mloc = fmaxf(mloc, s_mx[w]);
            e_reg = expf(v - mloc);
            s_w[t*256 + tid] = e_reg;           // raw u into history
            float es = warp_sum(e_reg);
            if (lane == 0) s_e[wl] = es;
        }
        __syncthreads();
        if (tid == 0) {
            float sl = 0.f;
            #pragma unroll
            for (int w = 0; w < 8; w++) sl += s_e[w];
            s_stat[r*2] = mloc; s_stat[r*2 + 1] = sl;
            #pragma unroll
            for (int i = 0; i < 3; i++) {
                peer[i][SM_STAT + r*2] = mloc;
                peer[i][SM_STAT + r*2 + 1] = sl;
            }
        }
        __syncthreads();                        // u visible block-locally

        // ===== S5: G partials (on raw u) + ra partials (on raw u), pushed =====
        if (wl < t) {
            const float4* wsp = (const float4*)(s_w + wl*256);
            const float4* wtp = (const float4*)(s_w + t*256);
            float4 a0 = wsp[lane], c0 = wtp[lane];
            float4 a1 = wsp[32 + lane], c1 = wtp[32 + lane];
            float g = a0.x*c0.x + a0.y*c0.y + a0.z*c0.z + a0.w*c0.w
                    + a1.x*c1.x + a1.y*c1.y + a1.z*c1.z + a1.w*c1.w;
            g = warp_sum(g);
            if (lane == 0) {
                int off = SM_GP + r*32 + wl;
                s_Gp[r*32 + wl] = g;
                peer[0][off] = g; peer[1][off] = g; peer[2][off] = g;
            }
        }
        {
            const float4* wtp = (const float4*)(s_w + t*256);
            const float4* at0 = (const float4*)(s_addr + wl*256);
            const float4* at1 = (const float4*)(s_addr + (wl + 32)*256);
            float4 w0 = wtp[lane], w1 = wtp[32 + lane];
            float4 x0 = at0[lane], x1 = at0[32 + lane];
            float4 y0 = at1[lane], y1 = at1[32 + lane];
            float a0 = w0.x*x0.x + w0.y*x0.y + w0.z*x0.z + w0.w*x0.w
                     + w1.x*x1.x + w1.y*x1.y + w1.z*x1.z + w1.w*x1.w;
            float a1 = w0.x*y0.x + w0.y*y0.y + w0.z*y0.z + w0.w*y0.w
                     + w1.x*y1.x + w1.y*y1.y + w1.z*y1.z + w1.w*y1.w;
            a0 = warp_sum(a0);
            a1 = warp_sum(a1);
            if (lane == 0) {
                int off0 = SM_RAP + r*64 + wl;
                int off1 = SM_RAP + r*64 + wl + 32;
                s_rap[r*64 + wl] = a0;
                s_rap[r*64 + wl + 32] = a1;
                peer[0][off0] = a0; peer[1][off0] = a0; peer[2][off0] = a0;
                peer[0][off1] = a1; peer[1][off1] = a1; peer[2][off1] = a1;
            }
        }
        cl.sync();                              // [B] stats + G/ra partials visible

        // ===== S6: factors f_{t,r'}, then combine G + ra, then rc =====
        if (tid < 4) {
            const float* st = s_stat;
            float M = fmaxf(fmaxf(st[0], st[2]), fmaxf(st[4], st[6]));
            float Z = st[1]*expf(st[0] - M) + st[3]*expf(st[2] - M)
                    + st[5]*expf(st[4] - M) + st[7]*expf(st[6] - M);
            s_shist[tid*32 + t] = expf(st[tid*2] - M) / Z;
        }
        __syncthreads();
        if (tid < 32) {
            if (tid < t) {
                float acc = 0.f;
                #pragma unroll
                for (int rr2 = 0; rr2 < 4; rr2++)
                    acc += s_Gp[rr2*32 + tid]
                         * s_shist[rr2*32 + t] * s_shist[rr2*32 + tid];
                s_G[tid] = acc;
            }
        } else if (tid < 96) {
            int a = tid - 32;
            float acc = 0.f;
            #pragma unroll
            for (int rr2 = 0; rr2 < 4; rr2++)
                acc += s_rap[rr2*64 + a] * s_shist[rr2*32 + t];
            s_r[a] = acc;
        }
        __syncthreads();
        if (tid < 192) {
            float acc = 0.f;
            for (int s = 0; s < t; s++)
                acc += s_G[s] * s_cand[s*192 + tid];
            s_r[A_ + tid] = acc;
        }
        __syncthreads();

        // ===== S7: gm partials (24 warps, r's row quarter) =====
        if (wl < 24) {
            int g = wl >> 3, kq = wl & 7;
            int row = g*256 + r*64 + lane*2;
            int m0 = kq << 5;
            float a0 = 0.f, a1 = 0.f;
            #pragma unroll 8
            for (int m = m0; m < m0 + 32; m++) {
                float2 w = *(const float2*)(g_WmT + m*768 + row);
                float rm = s_r[m];
                a0 += w.x*rm; a1 += w.y*rm;
            }
            s_gmp[kq*192 + g*64 + lane*2    ] = a0;
            s_gmp[kq*192 + g*64 + lane*2 + 1] = a1;
        }
        __syncthreads();

        // ===== S8: gate combine + h slice update + broadcast =====
        if (tid < 64) {
            int hid = r*64 + tid;
            float gh0 = s_bh[tid],       gm0 = s_bm[tid];
            float gh1 = s_bh[64 + tid],  gm1 = s_bm[64 + tid];
            float gh2 = s_bh[128 + tid], gm2 = s_bm[128 + tid];
            #pragma unroll
            for (int kq = 0; kq < 8; kq++) {
                gh0 += s_ghp[kq*192 + tid];
                gh1 += s_ghp[kq*192 + 64 + tid];
                gh2 += s_ghp[kq*192 + 128 + tid];
                gm0 += s_gmp[kq*192 + tid];
                gm1 += s_gmp[kq*192 + 64 + tid];
                gm2 += s_gmp[kq*192 + 128 + tid];
            }
            float rr = 1.f / (1.f + expf(-(s_gi[tid] + gh0 + gm0)));
            float zz = 1.f / (1.f + expf(-(s_gi[64 + tid] + gh1 + gm1)));
            float nn = tanhf(s_gi[128 + tid] + gm2 + rr*gh2);
            float hn = (1.f - zz)*nn + zz*s_h[hid];
            int off = SM_H + hid;
            s_h[hid] = hn;
            peer[0][off] = hn; peer[1][off] = hn; peer[2][off] = hn;
            out[t*H_*B_ + hid*32 + b] = hn;
        }
        cl.sync();                              // [C] full h visible
    }

    // final head (t = T-1), rank 0
    if (rank == 0 && wl == 0) {
        float logit[10];
        float mx = -1e30f;
        #pragma unroll
        for (int o = 0; o < 10; o++) {
            float s = 0.f;
            #pragma unroll
            for (int j = 0; j < 8; j++) {
                int k = lane + 32*j;
                s += s_Wout[o*H_ + k] * s_h[k];
            }
            s = warp_sum(s);
            s += s_bo[o];
            logit[o] = s;
            mx = fmaxf(mx, s);
        }
        float se = 0.f;
        #pragma unroll
        for (int o = 0; o < 10; o++) se += expf(logit[o] - mx);
        float lse = mx + logf(se);
        if (lane == 0) {
            #pragma unroll
            for (int o = 0; o < 10; o++)
                out[HSOFF + ((T_-1)*10 + o)*B_ + b] = logit[o] - lse;
        }
    }
}

extern "C" void kernel_launch(void* const* d_in, const int* in_sizes, int n_in,
                              void* d_out, int out_size) {
    (void)in_sizes; (void)n_in; (void)out_size;
    const float* batch = (const float*)d_in[0];
    const float* Wi    = (const float*)d_in[1];
    const float* bi    = (const float*)d_in[2];
    const float* Wh    = (const float*)d_in[3];
    const float* bh    = (const float*)d_in[4];
    const float* Wm    = (const float*)d_in[5];
    const float* bm    = (const float*)d_in[6];
    const float* Wout  = (const float*)d_in[7];
    const float* bo    = (const float*)d_in[8];
    const float* addr  = (const float*)d_in[9];
    const float* Wq    = (const float*)d_in[10];
    const float* bq    = (const float*)d_in[11];
    const float* u     = (const float*)d_in[12];
    const float* Wch   = (const float*)d_in[13];
    const float* Wci   = (const float*)d_in[14];
    float* out = (float*)d_out;

    static int smem_set = 0;
    if (!smem_set) {
        cudaFuncSetAttribute((const void*)k_run,
                             cudaFuncAttributeMaxDynamicSharedMemorySize,
                             SMEM_FLOATS * 4);
        smem_set = 1;
    }
    k_tr<<<560, 256>>>(Wh, Wq, Wch, Wm, addr);
    k_init<<<1024, 256>>>(batch, Wi, bi, Wci);
    k_run<<<128, 1024, SMEM_FLOATS * 4>>>(bh, bq, u, bm, Wout, bo, out);
}